// round 11
// baseline (speedup 1.0000x reference)
#include <cuda_runtime.h>
#include <cuda_bf16.h>
#include <cstdint>

#define HH   128
#define LBn  64
#define PWn  32
#define WLn  96
#define WC   65
#define WCP  68
#define NCTA 64
#define TPB  256
#define FT_TILE (HH * HH)            // floats per step tile
#define DYN_SMEM (2 * FT_TILE * 4)   // 128 KB double-buffered FT

// ---------------- device scratch (no allocations allowed) ----------------
__device__ float g_FT[WLn * HH * HH];
__device__ float g_Pp[2][HH * HH];        // Ppred (pre-update covariance)
__device__ float g_Tg[2][HH * WCP];       // T (pre-update influence)
__device__ float g_vpart[2][NCTA][HH];    // partials of v = h^T Ppred
__device__ float g_qpart[2][NCTA][WCP];   // partials of q = h^T T
__device__ float g_urow[2][HH];           // u = Ppred h (full row vector)
__device__ float g_Wcf[HH * WCP];         // corrected Wc after filter step 63
__device__ float g_V[PWn][WCP];
// tree-barrier state: monotonic counters (no per-barrier reset needed);
// zeroed between graph replays by pred_chains. 128B padding per group counter.
__device__ unsigned int g_gcnt[8][32];
__device__ unsigned int g_rcnt;
__device__ unsigned int g_gen;

__device__ __forceinline__ float comp2(float2 v, int h) { return h ? v.y : v.x; }

// Atomic acquire load (NOT an RMW: no LTS atomic-ALU serialization).
__device__ __forceinline__ unsigned int ldacq_u32(const unsigned int* p) {
    unsigned int v;
    asm volatile("ld.global.acquire.gpu.u32 %0, [%1];" : "=r"(v) : "l"(p) : "memory");
    return v;
}

__device__ __forceinline__ void cp_async16(unsigned int saddr, const void* gptr) {
    asm volatile("cp.async.cg.shared.global [%0], [%1], 16;" :: "r"(saddr), "l"(gptr));
}

// Hierarchical grid barrier, ABSOLUTE generation n (0-based).
// 8 groups x 8 CTAs; counters are monotonic: during barrier n each group
// counter returns values n*8..n*8+7, so "old == n*8+7" identifies the last
// arriver without any reset (reset-race class eliminated). Root identical.
// Waiters poll g_gen with acquire loads (monotonic: stale reads only poll
// longer, never exit early). __threadfence() after (CCTL.IVALL) makes other
// SMs' plain stores visible to our plain loads.
__device__ __forceinline__ void gbar(unsigned int n, int cta) {
    __syncthreads();
    if (threadIdx.x == 0) {
        const unsigned int tgt = n * 8u + 7u;
        __threadfence();
        unsigned int a = atomicAdd(&g_gcnt[cta >> 3][0], 1u);
        if (a == tgt) {
            __threadfence();
            unsigned int b = atomicAdd(&g_rcnt, 1u);
            if (b == tgt) {
                __threadfence();
                atomicExch(&g_gen, n + 1u);
            } else {
                while ((int)(ldacq_u32(&g_gen) - (n + 1u)) < 0) { __nanosleep(32); }
            }
        } else {
            while ((int)(ldacq_u32(&g_gen) - (n + 1u)) < 0) { __nanosleep(32); }
        }
        __threadfence();
    }
    __syncthreads();
}

// ---------------------------------------------------------------------------
// Kernel 1: transpose the 96 F matrices (128x128) into g_FT.
// ---------------------------------------------------------------------------
__global__ void __launch_bounds__(256) transpose_f(const float* __restrict__ Fw) {
    const int t  = blockIdx.x;
    const int ti = blockIdx.y;
    __shared__ float s[32][33];
    const float* src = Fw + (size_t)t * HH * HH;
    float* dst = g_FT + (size_t)t * HH * HH;
    const int x  = threadIdx.x & 31;
    const int y0 = threadIdx.x >> 5;
    for (int tj = 0; tj < 4; tj++) {
        #pragma unroll
        for (int yy = 0; yy < 32; yy += 8)
            s[y0 + yy][x] = src[(ti * 32 + y0 + yy) * HH + tj * 32 + x];
        __syncthreads();
        #pragma unroll
        for (int yy = 0; yy < 32; yy += 8)
            dst[(tj * 32 + y0 + yy) * HH + ti * 32 + x] = s[x][y0 + yy];
        __syncthreads();
    }
}

// ---------------------------------------------------------------------------
// Kernel 2: persistent Kalman FILTER (64 steps, one tree-barrier each), then
// materialize the corrected influence matrix Wcf = T_63 - K_63 q~_63^T.
// Deferred rank-1 correction (v, q, u carried across the barrier).
// FT tiles double-buffered in dynamic smem via cp.async (prefetched 1 step
// ahead). CTA c owns rows {2c,2c+1}; thread (j = tid&127, h = tid>>7).
// ---------------------------------------------------------------------------
__global__ void __launch_bounds__(TPB, 1) kalman_persist(
    const float* __restrict__ Fw, const float* __restrict__ Fb,
    const float* __restrict__ Hw, const float* __restrict__ Hb,
    const float* __restrict__ istate, const float* __restrict__ icov,
    const float* __restrict__ Q, const float* __restrict__ R)
{
    extern __shared__ float sFT[];   // [2][HH*HH]
    const int c = blockIdx.x, tid = threadIdx.x;
    const int j = tid & 127, h = tid >> 7;
    const int row0 = c * 2;
    const int k0 = h * 64;
    const int myrow = row0 + h;
    const bool doT = (j < WC);

    __shared__ float  sh[2][HH];      // H_w rows, double buffered
    __shared__ float2 sF[2][HH];      // owned F rows, double buffered
    __shared__ float  sfbh[2][4];     // [buf][0..1]=F_b rows, [2]=H_b
    __shared__ float2 sA1p[2][HH];    // raw A1 partials per k-half
    __shared__ float2 sA[HH];         // corrected A1
    __shared__ float2 sPp_s[2][HH];   // loopB partials
    __shared__ float2 sTp[2][WC];     // raw T partials
    __shared__ float  svp[2][HH];     // v staging / vpart staging
    __shared__ float  sqs[2][WC];     // q staging / qpart staging
    __shared__ float  sred[2][3][4];  // shuffle stages [half][S,FK0,FK1][warp]

    const unsigned int sft_base = (unsigned int)__cvta_generic_to_shared(sFT);

    // ---- init ----
    const float qreg = Q[myrow * HH + j];      // Q is step-invariant: 1 load
    const float R0 = R[0];
    g_Pp[0][myrow * HH + j] = icov[myrow * HH + j];
    if (doT)
        g_Tg[0][myrow * WCP + j] = (j == 0) ? istate[myrow] : 0.f;
    // step-0 params into buffer 0
    if (tid < HH) {
        sh[0][tid] = Hw[tid];
        sF[0][tid] = make_float2(Fw[(size_t)row0 * HH + tid],
                                 Fw[(size_t)(row0 + 1) * HH + tid]);
    } else if (tid < HH + 2) {
        sfbh[0][tid - HH] = Fb[row0 + (tid - HH)];
    } else if (tid == HH + 2) {
        sfbh[0][2] = Hb[0];
    }
    // prefetch FT[0] into smem buffer 0
    {
        const float* src = g_FT + tid * 64;
        const unsigned int dst = sft_base + (unsigned int)tid * 256u;
        #pragma unroll
        for (int i = 0; i < 16; i++)
            cp_async16(dst + i * 16u, src + i * 4);
        asm volatile("cp.async.commit_group;");
    }
    int cur = 0, pb = 0;
    unsigned int nbar = 0;
    gbar(nbar++, c);

    // ======================= filter (64 steps) =======================
    for (int t = 0; t < LBn; t++) {
        const bool corr = (t >= 1);
        const float hbprev = sfbh[pb ^ 1][2];

        // ---- issue cp.async prefetch of FT[t+1] (consumed next step) ----
        if (t + 1 < LBn) {
            const float* src = g_FT + (size_t)(t + 1) * FT_TILE + tid * 64;
            const unsigned int dst = sft_base
                + (unsigned int)(((t + 1) & 1) * FT_TILE + tid * 64) * 4u;
            #pragma unroll
            for (int i = 0; i < 16; i++)
                cp_async16(dst + i * 16u, src + i * 4);
            asm volatile("cp.async.commit_group;");
        }

        // ---- previous-step partial reductions (issued BEFORE loop A so
        //      their L2 latency overlaps loop A's FMA stream) ----
        float vs = 0.f, qs = 0.f, uval = 0.f;
        if (corr) {
            uval = g_urow[cur][j];                 // u = Ppred_prev h_prev
            const int cc0 = h * 32;
            #pragma unroll
            for (int i = 0; i < 32; i++) vs += g_vpart[cur][cc0 + i][j];
            if (doT) {
                #pragma unroll
                for (int i = 0; i < 32; i++) qs += g_qpart[cur][cc0 + i][j];
            }
        }

        // ---- raw loops: A1 = F*Ppred_prev, Traw = F*T_prev ----
        float2 a1 = make_float2(0.f, 0.f);
        float2 tv = make_float2(0.f, 0.f);
        {
            const float* Pc = g_Pp[cur] + (size_t)k0 * HH + j;
            const float* Tc = g_Tg[cur] + (size_t)k0 * WCP + j;
            #pragma unroll 32
            for (int kk = 0; kk < 64; kk++) {
                float2 f = sF[pb][k0 + kk];
                float p = Pc[kk * HH];
                a1.x += f.x * p; a1.y += f.y * p;
                if (doT) {
                    float w = Tc[kk * WCP];
                    tv.x += f.x * w; tv.y += f.y * w;
                }
            }
        }

        sA1p[h][j] = a1;
        if (doT) sTp[h][j] = tv;
        svp[h][j] = vs;
        if (doT) sqs[h][j] = qs;
        __syncthreads();

        // ---- S, FK from u; v_j from vpart sums ----
        float v_j = 0.f, termS = 0.f, tf0 = 0.f, tf1 = 0.f;
        if (corr) {
            v_j = svp[0][j] + svp[1][j];
            termS = sh[pb ^ 1][j] * uval;          // h_{t-1}[j] * u[j]
            float2 f = sF[pb][j];                   // F_t[row][k=j]
            tf0 = f.x * uval; tf1 = f.y * uval;
        }
        #pragma unroll
        for (int o = 16; o > 0; o >>= 1) {
            termS += __shfl_xor_sync(0xffffffffu, termS, o);
            tf0   += __shfl_xor_sync(0xffffffffu, tf0, o);
            tf1   += __shfl_xor_sync(0xffffffffu, tf1, o);
        }
        if ((tid & 31) == 0) {
            const int w = (tid >> 5) & 3;
            sred[h][0][w] = termS; sred[h][1][w] = tf0; sred[h][2][w] = tf1;
        }
        __syncthreads();

        float FK0 = 0.f, FK1 = 0.f;
        if (corr) {
            float S = R0 + sred[h][0][0] + sred[h][0][1] + sred[h][0][2] + sred[h][0][3];
            float inv = 1.f / S;
            FK0 = (sred[h][1][0] + sred[h][1][1] + sred[h][1][2] + sred[h][1][3]) * inv;
            FK1 = (sred[h][2][0] + sred[h][2][1] + sred[h][2][2] + sred[h][2][3]) * inv;
        }
        float qt = 0.f;
        if (corr && doT)
            qt = sqs[0][j] + sqs[1][j]
               + (j == 0 ? hbprev : 0.f) - (j == t ? 1.f : 0.f);

        // ---- combine + corrections (right vector is v, NOT u) ----
        if (h == 0) {
            float2 p0 = sA1p[0][j], p1 = sA1p[1][j];
            sA[j] = make_float2(p0.x + p1.x - FK0 * v_j,
                                p0.y + p1.y - FK1 * v_j);
        }
        float Tval = 0.f;
        if (doT) {
            Tval = comp2(sTp[0][j], h) + comp2(sTp[1][j], h)
                 - (h ? FK1 : FK0) * qt;
            if (j == 0) Tval += sfbh[pb][h];
        }
        // FT[t] must be resident before loop B (<=1 group may remain in flight)
        if (t + 1 < LBn) asm volatile("cp.async.wait_group 1;");
        else             asm volatile("cp.async.wait_group 0;");
        __syncthreads();

        // ---- loopB: Ppred = A1 * FT + Q  (FT from smem) ----
        float2 pr = make_float2(0.f, 0.f);
        {
            const float* FTs = sFT + (t & 1) * FT_TILE + k0 * HH + j;
            #pragma unroll 32
            for (int kk = 0; kk < 64; kk++) {
                float ft = FTs[kk * HH];
                float2 a = sA[k0 + kk];
                pr.x += a.x * ft; pr.y += a.y * ft;
            }
        }
        sPp_s[h][j] = pr;
        __syncthreads();
        const float ppf = comp2(sPp_s[0][j], h) + comp2(sPp_s[1][j], h) + qreg;

        // ---- writes: Ppred rows, T rows, v/q partials, u rows ----
        const int nxt = cur ^ 1;
        g_Pp[nxt][myrow * HH + j] = ppf;
        if (doT) g_Tg[nxt][myrow * WCP + j] = Tval;
        const float hr = sh[pb][myrow];
        svp[h][j] = hr * ppf;
        if (doT) sqs[h][j] = hr * Tval;
        // u[myrow] = sum_j Ppred[myrow][j] * h_t[j]
        {
            float uv = ppf * sh[pb][j];
            #pragma unroll
            for (int o = 16; o > 0; o >>= 1)
                uv += __shfl_xor_sync(0xffffffffu, uv, o);
            if ((tid & 31) == 0) sred[h][0][(tid >> 5) & 3] = uv;
        }
        __syncthreads();
        if (tid < HH)
            g_vpart[nxt][c][tid] = svp[0][tid] + svp[1][tid];
        else if (tid - HH < WC)
            g_qpart[nxt][c][tid - HH] = sqs[0][tid - HH] + sqs[1][tid - HH];
        if (j == 0)
            g_urow[nxt][myrow] = sred[h][0][0] + sred[h][0][1]
                               + sred[h][0][2] + sred[h][0][3];

        // ---- prefetch step t+1 params (ordered by gbar's entry sync) ----
        {
            const int t1 = t + 1, nb = pb ^ 1;
            if (tid < HH) {
                sh[nb][tid] = Hw[t1 * HH + tid];
                sF[nb][tid] = make_float2(Fw[((size_t)t1 * HH + row0) * HH + tid],
                                          Fw[((size_t)t1 * HH + row0 + 1) * HH + tid]);
            } else if (tid < HH + 2) {
                sfbh[nb][tid - HH] = Fb[t1 * HH + row0 + (tid - HH)];
            } else if (tid == HH + 2) {
                sfbh[nb][2] = Hb[t1];
            }
        }

        gbar(nbar++, c);
        cur ^= 1; pb ^= 1;
    }

    // ---- materialize Wcf = T_63 - (u/S) q~^T ----
    {
        const float hb63 = sfbh[pb ^ 1][2];
        const float uj = g_urow[cur][j];
        float termS = sh[pb ^ 1][j] * uj;
        #pragma unroll
        for (int o = 16; o > 0; o >>= 1)
            termS += __shfl_xor_sync(0xffffffffu, termS, o);
        if ((tid & 31) == 0) sred[h][0][(tid >> 5) & 3] = termS;
        float qs = 0.f;
        if (doT) {
            const int cc0 = h * 32;
            #pragma unroll
            for (int i = 0; i < 32; i++) qs += g_qpart[cur][cc0 + i][j];
            sqs[h][j] = qs;
        }
        __syncthreads();
        const float S = R0 + sred[h][0][0] + sred[h][0][1]
                           + sred[h][0][2] + sred[h][0][3];
        if (doT) {
            const float Krow = g_urow[cur][myrow] / S;
            const float qt = sqs[0][j] + sqs[1][j]
                           + (j == 0 ? hb63 : 0.f) - (j == LBn ? 1.f : 0.f);
            g_Wcf[myrow * WCP + j] = g_Tg[cur][myrow * WCP + j] - Krow * qt;
        }
    }
}

// ---------------------------------------------------------------------------
// Kernel 3: prediction chains — CTA m computes V row m with NO grid barriers.
//   r = Hw[64+m]; bias = Hb[64+m]; for i = 64+m..64: bias += r.Fb_i; r = F_i^T r
//   V[m][j] = r^T Wcf[:,j]  (+bias on const column)
// Also resets the tree-barrier counters for the next graph replay.
// ---------------------------------------------------------------------------
__global__ void __launch_bounds__(256) pred_chains(
    const float* __restrict__ Fw, const float* __restrict__ Fb,
    const float* __restrict__ Hw, const float* __restrict__ Hb)
{
    const int m = blockIdx.x;
    const int tid = threadIdx.x;
    const int j = tid & 127, h = tid >> 7;
    const int k0 = h * 64;

    // reset barrier state (persist kernel has fully completed in stream order)
    if (m == 0) {
        if (tid == 0) { g_gen = 0u; g_rcnt = 0u; }
        if (tid < 8) g_gcnt[tid][0] = 0u;
    }

    __shared__ float r[2][HH];
    __shared__ float rp[2][HH];
    __shared__ float sfb[HH];
    __shared__ float sbias[2];

    if (tid < HH) r[0][tid] = Hw[(LBn + m) * HH + tid];
    float bias = Hb[LBn + m];
    __syncthreads();

    int rb = 0;
    for (int i = LBn + m; i >= LBn; --i) {
        if (tid < HH) sfb[tid] = Fb[i * HH + tid];
        __syncthreads();
        float rn = 0.f, bp = 0.f;
        const float* Fi = Fw + (size_t)i * HH * HH + (size_t)k0 * HH + j;
        #pragma unroll 16
        for (int kk = 0; kk < 64; kk++) {
            float rk = r[rb][k0 + kk];
            rn += Fi[kk * HH] * rk;
            bp += sfb[k0 + kk] * rk;
        }
        rp[h][j] = rn;
        if (j == 0) sbias[h] = bp;
        __syncthreads();
        if (tid < HH) r[rb ^ 1][tid] = rp[0][tid] + rp[1][tid];
        bias += sbias[0] + sbias[1];
        __syncthreads();
        rb ^= 1;
    }

    if (j < WC) {
        float vn = 0.f;
        const float* Wf = g_Wcf + (size_t)k0 * WCP + j;
        #pragma unroll 16
        for (int kk = 0; kk < 64; kk++)
            vn += Wf[kk * WCP] * r[rb][k0 + kk];
        rp[h][j] = vn;
    }
    __syncthreads();
    if (tid < WC) {
        float s = rp[0][tid] + rp[1][tid];
        if (tid == 0) s += bias;
        g_V[m][tid] = s;
    }
}

// ---------------------------------------------------------------------------
// Kernel 4: out[b][p] = V[p][0] + sum_t V[p][1+t] x[b][t]
// CTA handles 8 batch rows: x loaded coalesced (float4) into smem;
// warp w = row b0+w, lane = p -> coalesced stores, conflict-free smem.
// ---------------------------------------------------------------------------
__global__ void __launch_bounds__(256) out_gemm(
    const float* __restrict__ x, float* __restrict__ out)
{
    __shared__ float sV[PWn][WC];
    __shared__ float sx[8][LBn];
    const int tid = threadIdx.x;
    const int b0 = blockIdx.x * 8;

    for (int e = tid; e < PWn * WC; e += 256) {
        int p = e / WC, jj = e % WC;
        sV[p][jj] = g_V[p][jj];
    }
    if (tid < 128) {   // 8 rows x 16 float4 = 128
        const int row = tid >> 4, seg = tid & 15;
        float4 v = *(const float4*)(x + (size_t)(b0 + row) * LBn + seg * 4);
        sx[row][seg * 4 + 0] = v.x; sx[row][seg * 4 + 1] = v.y;
        sx[row][seg * 4 + 2] = v.z; sx[row][seg * 4 + 3] = v.w;
    }
    __syncthreads();

    const int w = tid >> 5, p = tid & 31;
    float acc = sV[p][0];
    #pragma unroll 16
    for (int tt = 0; tt < LBn; tt++)
        acc += sV[p][1 + tt] * sx[w][tt];
    out[(size_t)(b0 + w) * PWn + p] = acc;
}

// ---------------------------------------------------------------------------
extern "C" void kernel_launch(void* const* d_in, const int* in_sizes, int n_in,
                              void* d_out, int out_size) {
    const float* x   = (const float*)d_in[0];
    const float* Fw  = (const float*)d_in[1];
    const float* Fb  = (const float*)d_in[2];
    const float* Hw  = (const float*)d_in[3];
    const float* Hb  = (const float*)d_in[4];
    const float* ist = (const float*)d_in[5];
    const float* icv = (const float*)d_in[6];
    const float* Q   = (const float*)d_in[7];
    const float* R   = (const float*)d_in[8];

    cudaFuncSetAttribute(kalman_persist,
                         cudaFuncAttributeMaxDynamicSharedMemorySize, DYN_SMEM);

    dim3 tgrid(WLn, 4);
    transpose_f<<<tgrid, 256>>>(Fw);
    kalman_persist<<<NCTA, TPB, DYN_SMEM>>>(Fw, Fb, Hw, Hb, ist, icv, Q, R);
    pred_chains<<<PWn, 256>>>(Fw, Fb, Hw, Hb);
    out_gemm<<<8192 / 8, 256>>>(x, (float*)d_out);
}

// round 12
// speedup vs baseline: 1.1803x; 1.1803x over previous
#include <cuda_runtime.h>
#include <cuda_bf16.h>
#include <cstdint>

#define HH   128
#define LBn  64
#define PWn  32
#define WLn  96
#define WC   65
#define WCP  68

// ---------------- device scratch (no allocations allowed) ----------------
__device__ float g_FT[WLn * HH * HH];
__device__ float g_Pp[2][HH * HH];        // Ppred (pre-update covariance)
__device__ float g_Tg[2][HH * WCP];       // T (pre-update influence)
__device__ float g_vpart[2][16][HH];      // partials of v = h^T Ppred
__device__ float g_qpart[2][16][WCP];     // partials of q = h^T T
__device__ float g_urow[2][HH];           // u = Ppred h (row vector)
__device__ float g_Wcf[HH * WCP];         // corrected Wc after filter step 63
__device__ float g_V[PWn][WCP];

#define CLUSTER_ARRIVE() asm volatile("barrier.cluster.arrive.aligned;" ::: "memory")
#define CLUSTER_WAIT()   asm volatile("barrier.cluster.wait.aligned;" ::: "memory")

// ---------------------------------------------------------------------------
// Kernel 1: transpose the 96 F matrices (128x128) into g_FT.
// ---------------------------------------------------------------------------
__global__ void __launch_bounds__(256) transpose_f(const float* __restrict__ Fw) {
    const int t  = blockIdx.x;
    const int ti = blockIdx.y;
    __shared__ float s[32][33];
    const float* src = Fw + (size_t)t * HH * HH;
    float* dst = g_FT + (size_t)t * HH * HH;
    const int x  = threadIdx.x & 31;
    const int y0 = threadIdx.x >> 5;
    for (int tj = 0; tj < 4; tj++) {
        #pragma unroll
        for (int yy = 0; yy < 32; yy += 8)
            s[y0 + yy][x] = src[(ti * 32 + y0 + yy) * HH + tj * 32 + x];
        __syncthreads();
        #pragma unroll
        for (int yy = 0; yy < 32; yy += 8)
            dst[(tj * 32 + y0 + yy) * HH + ti * 32 + x] = s[x][y0 + yy];
        __syncthreads();
    }
}

// ---------------------------------------------------------------------------
// Kernel 2: persistent Kalman FILTER as ONE CTA-cluster (CCTA CTAs), one
// hardware cluster.sync per step (release/acquire at cluster scope orders the
// global-memory exchange; HW flushes L1D). Deferred rank-1 algebra exactly as
// round 9:  F*P_new = F*Ppred - (F*u/S) v^T ;  F*Wc_new = F*T - (F*u/S) q~^T.
// CTA c owns rows [c*RPC, (c+1)*RPC). Thread (j = tid&127, h = tid>>7):
//   k-loops: partial sums over k-quarter [32h, 32h+32), all RPC rows
//   epilogue: owns rows rbase = c*RPC + h*RPP + i (i < RPP), column j.
// Staging arrays are r-major [4][RPC][128] -> conflict-free scalar LDS/STS.
// ---------------------------------------------------------------------------
template<int CCTA>
__global__ void __launch_bounds__(512, 1) kalman_persist_t(
    const float* __restrict__ Fw, const float* __restrict__ Fb,
    const float* __restrict__ Hw, const float* __restrict__ Hb,
    const float* __restrict__ istate, const float* __restrict__ icov,
    const float* __restrict__ Q, const float* __restrict__ R)
{
    constexpr int RPC = HH / CCTA;   // rows per CTA (8 or 16)
    constexpr int RPP = RPC / 4;     // rows per (j,h) thread (2 or 4)

    extern __shared__ float dyn[];
    float* sA1p = dyn;                     // [4][RPC][128] raw A1 partials
    float* sPp  = sA1p + 4 * RPC * HH;     // [4][RPC][128] loopB partials
    float* sTp  = sPp  + 4 * RPC * HH;     // [4][RPC][128] raw T partials
    float* sA   = sTp  + 4 * RPC * HH;     // [128][RPC] corrected A1 (k-major)

    __shared__ float sh[2][HH];            // H_w rows, double buffered
    __shared__ float sF[2][HH][RPC];       // F rows (k-major), double buffered
    __shared__ float sfb[2][RPC];          // F_b slices
    __shared__ float shb[2];               // H_b
    __shared__ float svp[4][HH];           // v contributions per h
    __shared__ float sqs[4][HH];           // q contributions per h
    __shared__ float sredS[4][4];          // termS partials [h][warp]
    __shared__ float sredk[4][4][RPP];     // tf partials [h][warp][i]
    __shared__ float sured[4][4][RPP];     // u partials  [h][warp][i]

    const int c = blockIdx.x, tid = threadIdx.x;
    const int j = tid & 127, h = tid >> 7;     // h = k-quarter
    const int k0 = h * 32;
    const int row0 = c * RPC;
    const int rbase = row0 + h * RPP;
    const bool doT = (j < WC);
    const int w = (tid >> 5) & 3;              // warp-in-group

    const float R0 = R[0];
    float qreg[RPP];
    #pragma unroll
    for (int i = 0; i < RPP; i++) qreg[i] = Q[(rbase + i) * HH + j];

    // ---- init: P0 = init_cov, T0 col0 = init_state ----
    #pragma unroll
    for (int i = 0; i < RPP; i++) {
        g_Pp[0][(rbase + i) * HH + j] = icov[(rbase + i) * HH + j];
        if (doT)
            g_Tg[0][(rbase + i) * WCP + j] = (j == 0) ? istate[rbase + i] : 0.f;
    }
    // step-0 params into buffer 0
    for (int e = tid; e < RPC * HH; e += 512) {
        int r = e >> 7, k = e & 127;
        sF[0][k][r] = Fw[((size_t)0 * HH + row0 + r) * HH + k];
    }
    if (tid < HH) sh[0][tid] = Hw[tid];
    else if (tid < HH + RPC) sfb[0][tid - HH] = Fb[row0 + (tid - HH)];
    else if (tid == HH + RPC) shb[0] = Hb[0];

    CLUSTER_ARRIVE(); CLUSTER_WAIT();

    int cur = 0, pb = 0;

    // ======================= filter (64 steps) =======================
    for (int t = 0; t < LBn; t++) {
        const bool corr = (t >= 1);
        const float hbprev = shb[pb ^ 1];

        // ---- previous-step reductions (full sums; only CCTA terms) ----
        float vs = 0.f, qs = 0.f, uval = 0.f;
        if (corr) {
            uval = g_urow[cur][j];
            #pragma unroll
            for (int i = 0; i < CCTA; i++) vs += g_vpart[cur][i][j];
            if (doT) {
                #pragma unroll
                for (int i = 0; i < CCTA; i++) qs += g_qpart[cur][i][j];
            }
        }

        // ---- raw loops over k-quarter: A1 = F*Ppred, Traw = F*T ----
        float a1[RPC], tv[RPC];
        #pragma unroll
        for (int r = 0; r < RPC; r++) { a1[r] = 0.f; tv[r] = 0.f; }
        {
            const float* Pc = g_Pp[cur] + (size_t)k0 * HH + j;
            const float* Tc = g_Tg[cur] + (size_t)k0 * WCP + j;
            #pragma unroll 8
            for (int kk = 0; kk < 32; kk++) {
                float p = Pc[kk * HH];
                float ww = doT ? Tc[kk * WCP] : 0.f;
                const float* fr = &sF[pb][k0 + kk][0];
                #pragma unroll
                for (int rr = 0; rr < RPC; rr += 4) {
                    float4 f = *(const float4*)(fr + rr);
                    a1[rr]   += f.x * p;  a1[rr+1] += f.y * p;
                    a1[rr+2] += f.z * p;  a1[rr+3] += f.w * p;
                    tv[rr]   += f.x * ww; tv[rr+1] += f.y * ww;
                    tv[rr+2] += f.z * ww; tv[rr+3] += f.w * ww;
                }
            }
        }
        // stage raw partials (r-major: conflict-free)
        #pragma unroll
        for (int r = 0; r < RPC; r++) {
            sA1p[((h * RPC) + r) * HH + j] = a1[r];
            sTp [((h * RPC) + r) * HH + j] = tv[r];
        }
        __syncthreads();

        // ---- S, FK from u (rank-1 ingredients of step t-1) ----
        float termS = corr ? sh[pb ^ 1][j] * uval : 0.f;
        float tf[RPP];
        #pragma unroll
        for (int i = 0; i < RPP; i++)
            tf[i] = corr ? sF[pb][j][h * RPP + i] * uval : 0.f;
        #pragma unroll
        for (int o = 16; o > 0; o >>= 1) {
            termS += __shfl_xor_sync(0xffffffffu, termS, o);
            #pragma unroll
            for (int i = 0; i < RPP; i++)
                tf[i] += __shfl_xor_sync(0xffffffffu, tf[i], o);
        }
        if ((tid & 31) == 0) {
            sredS[h][w] = termS;
            #pragma unroll
            for (int i = 0; i < RPP; i++) sredk[h][w][i] = tf[i];
        }
        __syncthreads();

        float FK[RPP];
        #pragma unroll
        for (int i = 0; i < RPP; i++) FK[i] = 0.f;
        if (corr) {
            float S = R0 + sredS[h][0] + sredS[h][1] + sredS[h][2] + sredS[h][3];
            float inv = 1.f / S;
            #pragma unroll
            for (int i = 0; i < RPP; i++)
                FK[i] = (sredk[h][0][i] + sredk[h][1][i]
                       + sredk[h][2][i] + sredk[h][3][i]) * inv;
        }
        float qt = 0.f;
        if (corr && doT)
            qt = qs + (j == 0 ? hbprev : 0.f) - (j == t ? 1.f : 0.f);

        // ---- combine + corrections (right vector is v, NOT u) ----
        float Tval[RPP];
        #pragma unroll
        for (int i = 0; i < RPP; i++) {
            const int r = h * RPP + i;
            float s = sA1p[(0 * RPC + r) * HH + j] + sA1p[(1 * RPC + r) * HH + j]
                    + sA1p[(2 * RPC + r) * HH + j] + sA1p[(3 * RPC + r) * HH + j];
            sA[j * RPC + r] = s - FK[i] * vs;
            float tt = sTp[(0 * RPC + r) * HH + j] + sTp[(1 * RPC + r) * HH + j]
                     + sTp[(2 * RPC + r) * HH + j] + sTp[(3 * RPC + r) * HH + j];
            Tval[i] = tt - FK[i] * qt + ((j == 0) ? sfb[pb][r] : 0.f);
        }
        __syncthreads();

        // ---- loop B: Ppred = A1 * F^T + Q (FT from L2, sA broadcast) ----
        float pr[RPC];
        #pragma unroll
        for (int r = 0; r < RPC; r++) pr[r] = 0.f;
        {
            const float* FTt = g_FT + (size_t)t * HH * HH + (size_t)k0 * HH + j;
            #pragma unroll 8
            for (int kk = 0; kk < 32; kk++) {
                float ft = FTt[kk * HH];
                const float* ar = &sA[(k0 + kk) * RPC];
                #pragma unroll
                for (int rr = 0; rr < RPC; rr += 4) {
                    float4 a = *(const float4*)(ar + rr);
                    pr[rr]   += a.x * ft; pr[rr+1] += a.y * ft;
                    pr[rr+2] += a.z * ft; pr[rr+3] += a.w * ft;
                }
            }
        }
        #pragma unroll
        for (int r = 0; r < RPC; r++)
            sPp[((h * RPC) + r) * HH + j] = pr[r];
        __syncthreads();

        // ---- combine P, write state + partials ----
        float ppf[RPP];
        #pragma unroll
        for (int i = 0; i < RPP; i++) {
            const int r = h * RPP + i;
            ppf[i] = sPp[(0 * RPC + r) * HH + j] + sPp[(1 * RPC + r) * HH + j]
                   + sPp[(2 * RPC + r) * HH + j] + sPp[(3 * RPC + r) * HH + j]
                   + qreg[i];
        }
        const int nxt = cur ^ 1;
        #pragma unroll
        for (int i = 0; i < RPP; i++)
            g_Pp[nxt][(rbase + i) * HH + j] = ppf[i];
        if (doT) {
            #pragma unroll
            for (int i = 0; i < RPP; i++)
                g_Tg[nxt][(rbase + i) * WCP + j] = Tval[i];
        }
        // v/q contributions of my rows
        float vc = 0.f, qc = 0.f;
        #pragma unroll
        for (int i = 0; i < RPP; i++) {
            const float hr = sh[pb][rbase + i];
            vc += hr * ppf[i];
            qc += hr * Tval[i];
        }
        svp[h][j] = vc;
        sqs[h][j] = doT ? qc : 0.f;
        // u rows: u[rbase+i] = sum_j ppf[i] * h_t[j]
        {
            float uv[RPP];
            #pragma unroll
            for (int i = 0; i < RPP; i++) uv[i] = ppf[i] * sh[pb][j];
            #pragma unroll
            for (int o = 16; o > 0; o >>= 1) {
                #pragma unroll
                for (int i = 0; i < RPP; i++)
                    uv[i] += __shfl_xor_sync(0xffffffffu, uv[i], o);
            }
            if ((tid & 31) == 0) {
                #pragma unroll
                for (int i = 0; i < RPP; i++) sured[h][w][i] = uv[i];
            }
        }
        __syncthreads();
        if (j == 0) {
            #pragma unroll
            for (int i = 0; i < RPP; i++)
                g_urow[nxt][rbase + i] = sured[h][0][i] + sured[h][1][i]
                                       + sured[h][2][i] + sured[h][3][i];
        }
        if (h == 0)
            g_vpart[nxt][c][j] = svp[0][j] + svp[1][j] + svp[2][j] + svp[3][j];
        else if (h == 1 && doT)
            g_qpart[nxt][c][j] = sqs[0][j] + sqs[1][j] + sqs[2][j] + sqs[3][j];

        // ---- prefetch step t+1 params into the other buffer ----
        {
            const int t1 = t + 1, nb = pb ^ 1;
            for (int e = tid; e < RPC * HH; e += 512) {
                int r = e >> 7, k = e & 127;
                sF[nb][k][r] = Fw[((size_t)t1 * HH + row0 + r) * HH + k];
            }
            if (tid < HH) sh[nb][tid] = Hw[t1 * HH + tid];
            else if (tid < HH + RPC) sfb[nb][tid - HH] = Fb[t1 * HH + row0 + (tid - HH)];
            else if (tid == HH + RPC) shb[nb] = Hb[t1];
        }

        CLUSTER_ARRIVE(); CLUSTER_WAIT();
        cur ^= 1; pb ^= 1;
    }

    // ---- epilogue: Wcf = T_63 - (u/S) q~^T ----
    {
        const float hb63 = shb[pb ^ 1];
        const float uval = g_urow[cur][j];
        float termS = sh[pb ^ 1][j] * uval;
        #pragma unroll
        for (int o = 16; o > 0; o >>= 1)
            termS += __shfl_xor_sync(0xffffffffu, termS, o);
        if ((tid & 31) == 0) sredS[h][w] = termS;
        float qsum = 0.f;
        if (doT) {
            #pragma unroll
            for (int i = 0; i < CCTA; i++) qsum += g_qpart[cur][i][j];
        }
        __syncthreads();
        const float S = R0 + sredS[h][0] + sredS[h][1] + sredS[h][2] + sredS[h][3];
        if (doT) {
            const float qt = qsum + (j == 0 ? hb63 : 0.f) - (j == LBn ? 1.f : 0.f);
            #pragma unroll
            for (int i = 0; i < RPP; i++) {
                const float Krow = g_urow[cur][rbase + i] / S;
                g_Wcf[(rbase + i) * WCP + j] =
                    g_Tg[cur][(rbase + i) * WCP + j] - Krow * qt;
            }
        }
    }
}

// ---------------------------------------------------------------------------
// Kernel 3: prediction chains — CTA m computes V row m, no grid barriers.
// ---------------------------------------------------------------------------
__global__ void __launch_bounds__(256) pred_chains(
    const float* __restrict__ Fw, const float* __restrict__ Fb,
    const float* __restrict__ Hw, const float* __restrict__ Hb)
{
    const int m = blockIdx.x;
    const int tid = threadIdx.x;
    const int j = tid & 127, h = tid >> 7;
    const int k0 = h * 64;

    __shared__ float r[2][HH];
    __shared__ float rp[2][HH];
    __shared__ float sfb[HH];
    __shared__ float sbias[2];

    if (tid < HH) r[0][tid] = Hw[(LBn + m) * HH + tid];
    float bias = Hb[LBn + m];
    __syncthreads();

    int rb = 0;
    for (int i = LBn + m; i >= LBn; --i) {
        if (tid < HH) sfb[tid] = Fb[i * HH + tid];
        __syncthreads();
        float rn = 0.f, bp = 0.f;
        const float* Fi = Fw + (size_t)i * HH * HH + (size_t)k0 * HH + j;
        #pragma unroll 16
        for (int kk = 0; kk < 64; kk++) {
            float rk = r[rb][k0 + kk];
            rn += Fi[kk * HH] * rk;
            bp += sfb[k0 + kk] * rk;
        }
        rp[h][j] = rn;
        if (j == 0) sbias[h] = bp;
        __syncthreads();
        if (tid < HH) r[rb ^ 1][tid] = rp[0][tid] + rp[1][tid];
        bias += sbias[0] + sbias[1];
        __syncthreads();
        rb ^= 1;
    }

    if (j < WC) {
        float vn = 0.f;
        const float* Wf = g_Wcf + (size_t)k0 * WCP + j;
        #pragma unroll 16
        for (int kk = 0; kk < 64; kk++)
            vn += Wf[kk * WCP] * r[rb][k0 + kk];
        rp[h][j] = vn;
    }
    __syncthreads();
    if (tid < WC) {
        float s = rp[0][tid] + rp[1][tid];
        if (tid == 0) s += bias;
        g_V[m][tid] = s;
    }
}

// ---------------------------------------------------------------------------
// Kernel 4: out[b][p] = V[p][0] + sum_t V[p][1+t] x[b][t]
// ---------------------------------------------------------------------------
__global__ void __launch_bounds__(256) out_gemm(
    const float* __restrict__ x, float* __restrict__ out)
{
    __shared__ float sV[PWn][WC];
    __shared__ float sx[8][LBn];
    const int tid = threadIdx.x;
    const int b0 = blockIdx.x * 8;

    for (int e = tid; e < PWn * WC; e += 256) {
        int p = e / WC, jj = e % WC;
        sV[p][jj] = g_V[p][jj];
    }
    if (tid < 128) {
        const int row = tid >> 4, seg = tid & 15;
        float4 v = *(const float4*)(x + (size_t)(b0 + row) * LBn + seg * 4);
        sx[row][seg * 4 + 0] = v.x; sx[row][seg * 4 + 1] = v.y;
        sx[row][seg * 4 + 2] = v.z; sx[row][seg * 4 + 3] = v.w;
    }
    __syncthreads();

    const int w = tid >> 5, p = tid & 31;
    float acc = sV[p][0];
    #pragma unroll 16
    for (int tt = 0; tt < LBn; tt++)
        acc += sV[p][1 + tt] * sx[w][tt];
    out[(size_t)(b0 + w) * PWn + p] = acc;
}

// ---------------------------------------------------------------------------
extern "C" void kernel_launch(void* const* d_in, const int* in_sizes, int n_in,
                              void* d_out, int out_size) {
    const float* x   = (const float*)d_in[0];
    const float* Fw  = (const float*)d_in[1];
    const float* Fb  = (const float*)d_in[2];
    const float* Hw  = (const float*)d_in[3];
    const float* Hb  = (const float*)d_in[4];
    const float* ist = (const float*)d_in[5];
    const float* icv = (const float*)d_in[6];
    const float* Q   = (const float*)d_in[7];
    const float* R   = (const float*)d_in[8];

    const int dyn16 = 13 * HH * 8  * 4;   // CCTA=16 (RPC=8):  53,248 B
    const int dyn8  = 13 * HH * 16 * 4;   // CCTA=8  (RPC=16): 106,496 B

    cudaFuncSetAttribute((const void*)kalman_persist_t<16>,
                         cudaFuncAttributeNonPortableClusterSizeAllowed, 1);
    cudaFuncSetAttribute((const void*)kalman_persist_t<16>,
                         cudaFuncAttributeMaxDynamicSharedMemorySize, dyn16);
    cudaFuncSetAttribute((const void*)kalman_persist_t<8>,
                         cudaFuncAttributeMaxDynamicSharedMemorySize, dyn8);

    dim3 tgrid(WLn, 4);
    transpose_f<<<tgrid, 256>>>(Fw);

    // Prefer a 16-CTA (nonportable) cluster; fall back to portable 8.
    bool launched16 = false;
    {
        cudaLaunchConfig_t cfg = {};
        cfg.gridDim = {16, 1, 1};
        cfg.blockDim = {512, 1, 1};
        cfg.dynamicSmemBytes = (size_t)dyn16;
        cudaLaunchAttribute at[1];
        at[0].id = cudaLaunchAttributeClusterDimension;
        at[0].val.clusterDim = {16, 1, 1};
        cfg.attrs = at; cfg.numAttrs = 1;
        int ncl = 0;
        cudaError_t e = cudaOccupancyMaxActiveClusters(&ncl, kalman_persist_t<16>, &cfg);
        if (e == cudaSuccess && ncl >= 1) {
            e = cudaLaunchKernelEx(&cfg, kalman_persist_t<16>,
                                   Fw, Fb, Hw, Hb, ist, icv, Q, R);
            launched16 = (e == cudaSuccess);
        }
        if (!launched16) (void)cudaGetLastError();   // clear error state
    }
    if (!launched16) {
        cudaLaunchConfig_t cfg = {};
        cfg.gridDim = {8, 1, 1};
        cfg.blockDim = {512, 1, 1};
        cfg.dynamicSmemBytes = (size_t)dyn8;
        cudaLaunchAttribute at[1];
        at[0].id = cudaLaunchAttributeClusterDimension;
        at[0].val.clusterDim = {8, 1, 1};
        cfg.attrs = at; cfg.numAttrs = 1;
        cudaLaunchKernelEx(&cfg, kalman_persist_t<8>,
                           Fw, Fb, Hw, Hb, ist, icv, Q, R);
    }

    pred_chains<<<PWn, 256>>>(Fw, Fb, Hw, Hb);
    out_gemm<<<8192 / 8, 256>>>(x, (float*)d_out);
}